// round 11
// baseline (speedup 1.0000x reference)
#include <cuda_runtime.h>
#include <cuda_bf16.h>
#include <math.h>
#include <stdint.h>

#define NN 100000
#define EE 1600000
#define DD 256
#define HH 512
#define LL 5
#define SCAN_B 512

// ---------------- device scratch (no allocs allowed) ----------------
__device__ float g_h[(size_t)NN * DD];
__device__ float g_agg[(size_t)NN * DD];       // z2 buffer (GEMM2 out)
__device__ float g_t1[(size_t)NN * HH];
__device__ float g_sum[HH];                    // zero-init; self-zeroed by bnfin
__device__ float g_sumsq[HH];
__device__ float g_a[HH];
__device__ float g_bc[HH];
// CSR build + permuted edge data
__device__ int g_off[NN + 1];
__device__ int g_cursor[NN];
__device__ int g_srcp[EE];
__device__ float g_attr8[(size_t)EE * 8];
// bf16 hi/lo split GEMM operands
__device__ __nv_bfloat16 g_Ab[(size_t)NN * 1024];        // A' [M][2K], K<=512
__device__ __nv_bfloat16 g_B1[(size_t)LL * 768 * 512];   // B1' [3K=768][N=512] k-major
__device__ __nv_bfloat16 g_B2[(size_t)LL * 1536 * 256];  // B2' [3K=1536][N=256]

// ================= PTX helpers =================
__device__ __forceinline__ uint32_t smem_u32(const void* p) {
    uint32_t a;
    asm("{ .reg .u64 t; cvta.to.shared.u64 t, %1; cvt.u32.u64 %0, t; }" : "=r"(a) : "l"(p));
    return a;
}
__device__ __forceinline__ void cpa16(uint32_t dst, const void* src, int sz) {
    asm volatile("cp.async.cg.shared.global [%0], [%1], 16, %2;"
                 :: "r"(dst), "l"(src), "r"(sz) : "memory");
}
#define CP_COMMIT() asm volatile("cp.async.commit_group;" ::: "memory")
#define CP_WAIT2()  asm volatile("cp.async.wait_group 2;" ::: "memory")

#define LDSM_X4(r, addr) \
    asm volatile("ldmatrix.sync.aligned.m8n8.x4.shared.b16 {%0,%1,%2,%3}, [%4];" \
        : "=r"((r)[0]), "=r"((r)[1]), "=r"((r)[2]), "=r"((r)[3]) : "r"(addr))
#define LDSM_X4T(r, addr) \
    asm volatile("ldmatrix.sync.aligned.m8n8.x4.trans.shared.b16 {%0,%1,%2,%3}, [%4];" \
        : "=r"((r)[0]), "=r"((r)[1]), "=r"((r)[2]), "=r"((r)[3]) : "r"(addr))
#define MMA16816(d, a, b0, b1) \
    asm volatile("mma.sync.aligned.m16n8k16.row.col.f32.bf16.bf16.f32 " \
        "{%0,%1,%2,%3}, {%4,%5,%6,%7}, {%8,%9}, {%0,%1,%2,%3};" \
        : "+f"((d)[0]), "+f"((d)[1]), "+f"((d)[2]), "+f"((d)[3]) \
        : "r"((a)[0]), "r"((a)[1]), "r"((a)[2]), "r"((a)[3]), "r"(b0), "r"(b1))

// ---------------- bf16 pack ----------------
__device__ __forceinline__ uint32_t pk_bf2(float a, float b) {
    __nv_bfloat162 t = __floats2bfloat162_rn(a, b);
    return *(uint32_t*)&t;
}

// ---------------- setup: h init + cursor zero + convB, one kernel ----------------
// blocks [0, M): h[bid] = emb[x[bid]], cursor[bid] = 0
// blocks [M, M + NBCONV): B' split conversion
#define NB1 (768 * 512)
#define NB2 (1536 * 256)
#define NBCONV ((LL * (NB1 + NB2)) / 256)
__global__ void k_setup(const int* __restrict__ x, const float* __restrict__ emb,
                        const float* __restrict__ W1, const float* __restrict__ W2, int M) {
    int bid = blockIdx.x, tid = threadIdx.x;
    if (bid < M) {
        g_h[(size_t)bid * DD + tid] = emb[(size_t)x[bid] * DD + tid];
        if (tid == 0) g_cursor[bid] = 0;
        return;
    }
    int idx = (bid - M) * 256 + tid;
    int l = idx / (NB1 + NB2);
    int r = idx % (NB1 + NB2);
    if (r < NB1) {
        int kk = r / 512, n = r % 512;
        int part = kk >> 8, k = kk & 255;
        float w = W1[(size_t)l * DD * HH + (size_t)k * HH + n];
        __nv_bfloat16 hi = __float2bfloat16(w);
        g_B1[(size_t)l * NB1 + r] =
            (part < 2) ? hi : __float2bfloat16(w - __bfloat162float(hi));
    } else {
        r -= NB1;
        int kk = r / 256, n = r % 256;
        int part = kk >> 9, k = kk & 511;
        float w = W2[(size_t)l * HH * DD + (size_t)k * DD + n];
        __nv_bfloat16 hi = __float2bfloat16(w);
        g_B2[(size_t)l * NB2 + r] =
            (part < 2) ? hi : __float2bfloat16(w - __bfloat162float(hi));
    }
}

// ---------------- hist ----------------
__global__ void k_hist(const int* __restrict__ dst, int E) {
    int e = blockIdx.x * blockDim.x + threadIdx.x;
    if (e < E) atomicAdd(&g_cursor[dst[e]], 1);
}

// ---------------- full scan, single block (writes g_off and g_cursor) ----------
__global__ void k_scanfull(int M) {
    __shared__ int s[SCAN_B];
    __shared__ int carry;
    int t = threadIdx.x;
    if (t == 0) { carry = 0; g_off[0] = 0; }
    __syncthreads();
    int nch = (M + SCAN_B - 1) / SCAN_B;
    for (int c = 0; c < nch; c++) {
        int i = c * SCAN_B + t;
        int v = (i < M) ? g_cursor[i] : 0;
        s[t] = v;
        __syncthreads();
        for (int d = 1; d < SCAN_B; d <<= 1) {
            int x = (t >= d) ? s[t - d] : 0;
            __syncthreads();
            s[t] += x;
            __syncthreads();
        }
        int incl = s[t] + carry;
        if (i < M) {
            g_off[i + 1] = incl;
            g_cursor[i] = incl - v;   // exclusive prefix = write cursor
        }
        __syncthreads();
        if (t == SCAN_B - 1) carry = incl;
        __syncthreads();
    }
}

// ---------------- scatter ----------------
__global__ void k_scatter(const int* __restrict__ src, const int* __restrict__ dst,
                          const float* __restrict__ attr, int E) {
    int e = blockIdx.x * blockDim.x + threadIdx.x;
    if (e < E) {
        int p = atomicAdd(&g_cursor[dst[e]], 1);
        g_srcp[p] = src[e];
        const float* at = attr + (size_t)e * 7;
        float* o = g_attr8 + (size_t)p * 8;
        *(float4*)(o) = make_float4(at[0], at[1], at[2], at[3]);
        *(float4*)(o + 4) = make_float4(at[4], at[5], at[6], 0.f);
    }
}

// ---------------- gather (+ fused A1' split-convert), reads g_h ----------------
__global__ void __launch_bounds__(256)
k_gather(const float* __restrict__ We, const float* __restrict__ be,
         const float* __restrict__ eps, int M) {
    int t = threadIdx.x;
    int cg = (t & 63) * 4;
    int n = blockIdx.x * 4 + (t >> 6);

    float4 w[7];
    #pragma unroll
    for (int k = 0; k < 7; k++) w[k] = *(const float4*)(We + k * DD + cg);
    float4 bev = *(const float4*)(be + cg);
    float e1 = 1.f + eps[0];

    if (n >= M) return;
    int p0 = g_off[n], p1 = g_off[n + 1];
    float4 acc = make_float4(0.f, 0.f, 0.f, 0.f);
    #pragma unroll 4
    for (int p = p0; p < p1; p++) {
        int s = g_srcp[p];
        float4 a0 = *(const float4*)(g_attr8 + (size_t)p * 8);
        float4 a1 = *(const float4*)(g_attr8 + (size_t)p * 8 + 4);
        float4 hv = *(const float4*)(g_h + (size_t)s * DD + cg);
        float4 emb = bev;
        emb.x = fmaf(a0.x, w[0].x, emb.x); emb.y = fmaf(a0.x, w[0].y, emb.y);
        emb.z = fmaf(a0.x, w[0].z, emb.z); emb.w = fmaf(a0.x, w[0].w, emb.w);
        emb.x = fmaf(a0.y, w[1].x, emb.x); emb.y = fmaf(a0.y, w[1].y, emb.y);
        emb.z = fmaf(a0.y, w[1].z, emb.z); emb.w = fmaf(a0.y, w[1].w, emb.w);
        emb.x = fmaf(a0.z, w[2].x, emb.x); emb.y = fmaf(a0.z, w[2].y, emb.y);
        emb.z = fmaf(a0.z, w[2].z, emb.z); emb.w = fmaf(a0.z, w[2].w, emb.w);
        emb.x = fmaf(a0.w, w[3].x, emb.x); emb.y = fmaf(a0.w, w[3].y, emb.y);
        emb.z = fmaf(a0.w, w[3].z, emb.z); emb.w = fmaf(a0.w, w[3].w, emb.w);
        emb.x = fmaf(a1.x, w[4].x, emb.x); emb.y = fmaf(a1.x, w[4].y, emb.y);
        emb.z = fmaf(a1.x, w[4].z, emb.z); emb.w = fmaf(a1.x, w[4].w, emb.w);
        emb.x = fmaf(a1.y, w[5].x, emb.x); emb.y = fmaf(a1.y, w[5].y, emb.y);
        emb.z = fmaf(a1.y, w[5].z, emb.z); emb.w = fmaf(a1.y, w[5].w, emb.w);
        emb.x = fmaf(a1.z, w[6].x, emb.x); emb.y = fmaf(a1.z, w[6].y, emb.y);
        emb.z = fmaf(a1.z, w[6].z, emb.z); emb.w = fmaf(a1.z, w[6].w, emb.w);
        acc.x += fmaxf(hv.x + emb.x, 0.f);
        acc.y += fmaxf(hv.y + emb.y, 0.f);
        acc.z += fmaxf(hv.z + emb.z, 0.f);
        acc.w += fmaxf(hv.w + emb.w, 0.f);
    }
    float4 hn = *(const float4*)(g_h + (size_t)n * DD + cg);
    float v0 = fmaf(e1, hn.x, acc.x), v1 = fmaf(e1, hn.y, acc.y);
    float v2 = fmaf(e1, hn.z, acc.z), v3 = fmaf(e1, hn.w, acc.w);
    float h0 = __bfloat162float(__float2bfloat16(v0));
    float h1 = __bfloat162float(__float2bfloat16(v1));
    float h2 = __bfloat162float(__float2bfloat16(v2));
    float h3 = __bfloat162float(__float2bfloat16(v3));
    uint2 hi = make_uint2(pk_bf2(h0, h1), pk_bf2(h2, h3));
    uint2 lo = make_uint2(pk_bf2(v0 - h0, v1 - h1), pk_bf2(v2 - h2, v3 - h3));
    *(uint2*)(g_Ab + (size_t)n * 512 + cg) = hi;
    *(uint2*)(g_Ab + (size_t)n * 512 + 256 + cg) = lo;
}

// A2' = split(relu(t1*a + bc)), [M][1024]
__global__ void k_convA2(int M) {
    int idx = blockIdx.x * 256 + threadIdx.x;
    if (idx >= M * 128) return;
    int row = idx >> 7, k = (idx & 127) * 4;
    size_t off = (size_t)row * HH + k;
    float4 t4 = *(const float4*)(g_t1 + off);
    float4 ca = *(const float4*)(g_a + k);
    float4 cb = *(const float4*)(g_bc + k);
    float v0 = fmaxf(fmaf(t4.x, ca.x, cb.x), 0.f);
    float v1 = fmaxf(fmaf(t4.y, ca.y, cb.y), 0.f);
    float v2 = fmaxf(fmaf(t4.z, ca.z, cb.z), 0.f);
    float v3 = fmaxf(fmaf(t4.w, ca.w, cb.w), 0.f);
    float h0 = __bfloat162float(__float2bfloat16(v0));
    float h1 = __bfloat162float(__float2bfloat16(v1));
    float h2 = __bfloat162float(__float2bfloat16(v2));
    float h3 = __bfloat162float(__float2bfloat16(v3));
    uint2 hi = make_uint2(pk_bf2(h0, h1), pk_bf2(h2, h3));
    uint2 lo = make_uint2(pk_bf2(v0 - h0, v1 - h1), pk_bf2(v2 - h2, v3 - h3));
    *(uint2*)(g_Ab + (size_t)row * 1024 + k) = hi;
    *(uint2*)(g_Ab + (size_t)row * 1024 + 512 + k) = lo;
}

// ---------------- HMMA GEMM, 4-stage cp.async pipeline, 2 CTAs/SM --------------
#define AP 80
#define BP 272
#define ASTG 10240
#define BSTG 8704
#define GSMEM (4 * (ASTG + BSTG) + 1024)

template <int NIT, int WRAP, int NC>
__global__ void __launch_bounds__(256, 2)
k_gemm_mma(const __nv_bfloat16* __restrict__ Abase, const __nv_bfloat16* __restrict__ Bbase,
           float* __restrict__ C, int M) {
    extern __shared__ char smem[];
    uint32_t sb = smem_u32(smem);
    uint32_t aB = sb, bB = sb + 4 * ASTG;
    float* ssum = (float*)(smem + 4 * (ASTG + BSTG));
    float* ssq = ssum + 128;

    int tid = threadIdx.x, lane = tid & 31, wid = tid >> 5;
    int wm = wid >> 1, wn = wid & 1;
    int brow = blockIdx.y * 128, bcol = blockIdx.x * 128;

    if (tid < 128) { ssum[tid] = 0.f; ssq[tid] = 0.f; }

    float acc[2][8][4];
    #pragma unroll
    for (int i = 0; i < 2; i++)
        #pragma unroll
        for (int j = 0; j < 8; j++)
            #pragma unroll
            for (int q = 0; q < 4; q++) acc[i][j][q] = 0.f;

    int arow = tid >> 1, ac16 = (tid & 1) * 2;
    int bkr = tid >> 3, bc16 = (tid & 7) * 2;

    auto load = [&](int s, int it) {
        int ac = it * 32; if (ac >= WRAP) ac -= WRAP;
        int ok = (brow + arow < M) ? 16 : 0;
        const char* srcA = (const char*)(Abase + (size_t)(brow + arow) * WRAP + ac);
        uint32_t dA = aB + s * ASTG + arow * AP;
        cpa16(dA + ac16 * 16, srcA + ac16 * 16, ok);
        cpa16(dA + ac16 * 16 + 16, srcA + ac16 * 16 + 16, ok);
        const char* srcB = (const char*)(Bbase + (size_t)(it * 32 + bkr) * NC + bcol);
        uint32_t dB = bB + s * BSTG + bkr * BP;
        cpa16(dB + bc16 * 16, srcB + bc16 * 16, 16);
        cpa16(dB + bc16 * 16 + 16, srcB + bc16 * 16 + 16, 16);
    };

    load(0, 0); CP_COMMIT();
    load(1, 1); CP_COMMIT();
    load(2, 2); CP_COMMIT();

    for (int i = 0; i < NIT; i++) {
        CP_WAIT2();          // stage i%4 complete
        __syncthreads();     // visible to all; all done reading stage (i+3)%4
        if (i + 3 < NIT) load((i + 3) % 4, i + 3);
        CP_COMMIT();

        int s = i % 4;
        uint32_t ab = aB + s * ASTG, bb = bB + s * BSTG;
        uint32_t a[2][2][4];
        #pragma unroll
        for (int mt = 0; mt < 2; mt++)
            #pragma unroll
            for (int kh = 0; kh < 2; kh++)
                LDSM_X4(a[mt][kh],
                        ab + (wm * 32 + mt * 16 + (lane & 15)) * AP +
                             (kh * 16 + (lane >> 4) * 8) * 2);
        #pragma unroll
        for (int nt2 = 0; nt2 < 4; nt2++) {
            uint32_t b0[4], b1[4];
            LDSM_X4T(b0, bb + (lane & 15) * BP +
                         (wn * 64 + nt2 * 16 + (lane >> 4) * 8) * 2);
            LDSM_X4T(b1, bb + (16 + (lane & 15)) * BP +
                         (wn * 64 + nt2 * 16 + (lane >> 4) * 8) * 2);
            #pragma unroll
            for (int mt = 0; mt < 2; mt++)
                #pragma unroll
                for (int j = 0; j < 2; j++) {
                    MMA16816(acc[mt][nt2 * 2 + j], a[mt][0], b0[j * 2], b0[j * 2 + 1]);
                    MMA16816(acc[mt][nt2 * 2 + j], a[mt][1], b1[j * 2], b1[j * 2 + 1]);
                }
        }
    }
    __syncthreads();

    // ---- epilogue: store C + fused BN stats ----
    int r0 = brow + wm * 32 + (lane >> 2);
    int cb = bcol + wn * 64 + (lane & 3) * 2;
    #pragma unroll
    for (int mt = 0; mt < 2; mt++)
        #pragma unroll
        for (int rh = 0; rh < 2; rh++) {
            int row = r0 + mt * 16 + rh * 8;
            if (row < M) {
                float* cr = C + (size_t)row * NC + cb;
                #pragma unroll
                for (int nt = 0; nt < 8; nt++)
                    *(float2*)(cr + nt * 8) =
                        make_float2(acc[mt][nt][rh * 2], acc[mt][nt][rh * 2 + 1]);
            }
        }
    #pragma unroll
    for (int nt = 0; nt < 8; nt++) {
        float s0 = 0.f, s1 = 0.f, q0 = 0.f, q1 = 0.f;
        #pragma unroll
        for (int mt = 0; mt < 2; mt++)
            #pragma unroll
            for (int rh = 0; rh < 2; rh++) {
                if (r0 + mt * 16 + rh * 8 < M) {
                    float v0 = acc[mt][nt][rh * 2], v1 = acc[mt][nt][rh * 2 + 1];
                    s0 += v0; q0 = fmaf(v0, v0, q0);
                    s1 += v1; q1 = fmaf(v1, v1, q1);
                }
            }
        int c = wn * 64 + nt * 8 + (lane & 3) * 2;
        atomicAdd(&ssum[c], s0);
        atomicAdd(&ssum[c + 1], s1);
        atomicAdd(&ssq[c], q0);
        atomicAdd(&ssq[c + 1], q1);
    }
    __syncthreads();
    if (tid < 128) {
        atomicAdd(&g_sum[bcol + tid], ssum[tid]);
        atomicAdd(&g_sumsq[bcol + tid], ssq[tid]);
    }
}

// ---------------- BN finalize (+ self-zero stats) ----------------
__global__ void k_bnfin(const float* __restrict__ g, const float* __restrict__ bt, float invM) {
    int c = blockIdx.x * blockDim.x + threadIdx.x;
    float mu = g_sum[c] * invM;
    float var = fmaf(-mu, mu, g_sumsq[c] * invM);
    float a = g[c] * rsqrtf(var + 1e-5f);
    g_a[c] = a;
    g_bc[c] = fmaf(-mu, a, bt[c]);
    g_sum[c] = 0.f;
    g_sumsq[c] = 0.f;
}

// ---------------- apply BN2 (+relu) ----------------
template <int TO_OUT>
__global__ void k_apply(float* __restrict__ out, int relu) {
    int idx = blockIdx.x * blockDim.x + threadIdx.x;
    float4 v = ((const float4*)g_agg)[idx];
    int c = (idx * 4) & (DD - 1);
    float4 a = *(const float4*)(g_a + c);
    float4 b = *(const float4*)(g_bc + c);
    v.x = fmaf(v.x, a.x, b.x);
    v.y = fmaf(v.y, a.y, b.y);
    v.z = fmaf(v.z, a.z, b.z);
    v.w = fmaf(v.w, a.w, b.w);
    if (relu) {
        v.x = fmaxf(v.x, 0.f); v.y = fmaxf(v.y, 0.f);
        v.z = fmaxf(v.z, 0.f); v.w = fmaxf(v.w, 0.f);
    }
    if (TO_OUT) ((float4*)out)[idx] = v;
    else        ((float4*)g_h)[idx] = v;
}

// ---------------- launcher ----------------
extern "C" void kernel_launch(void* const* d_in, const int* in_sizes, int n_in,
                              void* d_out, int out_size) {
    const int*   x        = (const int*)d_in[0];
    const int*   ei       = (const int*)d_in[1];
    const float* attr     = (const float*)d_in[2];
    const float* node_emb = (const float*)d_in[4];
    const float* We       = (const float*)d_in[5];
    const float* be       = (const float*)d_in[6];
    const float* W1       = (const float*)d_in[7];
    const float* g1       = (const float*)d_in[9];
    const float* bt1      = (const float*)d_in[10];
    const float* W2       = (const float*)d_in[11];
    const float* eps      = (const float*)d_in[13];
    const float* gbn      = (const float*)d_in[14];
    const float* bbn      = (const float*)d_in[15];
    float* out = (float*)d_out;

    int M = in_sizes[0];
    int E = in_sizes[1] / 2;
    const int* dst = ei + E;
    float invM = 1.0f / (float)M;

    // DEVICE addresses of __device__ globals
    void *pAb, *pB1, *pB2, *pT1, *pAgg;
    cudaGetSymbolAddress(&pAb, g_Ab);
    cudaGetSymbolAddress(&pB1, g_B1);
    cudaGetSymbolAddress(&pB2, g_B2);
    cudaGetSymbolAddress(&pT1, g_t1);
    cudaGetSymbolAddress(&pAgg, g_agg);
    const __nv_bfloat16* dAb = (const __nv_bfloat16*)pAb;
    const __nv_bfloat16* dB1 = (const __nv_bfloat16*)pB1;
    const __nv_bfloat16* dB2 = (const __nv_bfloat16*)pB2;
    float* dT1 = (float*)pT1;
    float* dAgg = (float*)pAgg;

    cudaFuncSetAttribute(k_gemm_mma<24, 512, 512>,
                         cudaFuncAttributeMaxDynamicSharedMemorySize, GSMEM);
    cudaFuncSetAttribute(k_gemm_mma<48, 1024, 256>,
                         cudaFuncAttributeMaxDynamicSharedMemorySize, GSMEM);

    int ewGrid = (M * DD / 4 + 255) / 256;
    int ntm = (M + 127) / 128;
    dim3 g1grid(HH / 128, ntm), g2grid(DD / 128, ntm);

    // ---- launch #1..#5: setup + CSR + gather(l=0); #6 = GEMM1 (profiled) ----
    k_setup<<<M + NBCONV, 256>>>(x, node_emb, W1, W2, M);          // 1
    k_hist<<<(E + 255) / 256, 256>>>(dst, E);                       // 2
    k_scanfull<<<1, SCAN_B>>>(M);                                   // 3
    k_scatter<<<(E + 255) / 256, 256>>>(ei, dst, attr, E);          // 4

    for (int l = 0; l < LL; l++) {
        k_gather<<<(M + 3) / 4, 256>>>(We + (size_t)l * 7 * DD, be + (size_t)l * DD,
                                       eps + l, M);                 // 5 (l=0)

        k_gemm_mma<24, 512, 512><<<g1grid, 256, GSMEM>>>(
            dAb, dB1 + (size_t)l * 768 * 512, dT1, M);              // 6 (l=0) <- ncu
        k_bnfin<<<HH / 256, 256>>>(g1 + (size_t)l * HH, bt1 + (size_t)l * HH, invM);

        k_convA2<<<(M * 128 + 255) / 256, 256>>>(M);
        k_gemm_mma<48, 1024, 256><<<g2grid, 256, GSMEM>>>(
            dAb, dB2 + (size_t)l * 1536 * 256, dAgg, M);
        k_bnfin<<<DD / 256, 256>>>(gbn + (size_t)l * DD, bbn + (size_t)l * DD, invM);

        if (l == LL - 1) k_apply<1><<<ewGrid, 256>>>(out, 0);
        else             k_apply<0><<<ewGrid, 256>>>(out, 1);
    }
}

// round 12
// speedup vs baseline: 1.0182x; 1.0182x over previous
#include <cuda_runtime.h>
#include <cuda_bf16.h>
#include <math.h>
#include <stdint.h>

#define NN 100000
#define EE 1600000
#define DD 256
#define HH 512
#define LL 5
#define SCAN_B 512

// ---------------- device scratch (no allocs allowed) ----------------
__device__ float g_h[(size_t)NN * DD];
__device__ float g_agg[(size_t)NN * DD];       // z2 buffer (GEMM2 out)
__device__ float g_t1[(size_t)NN * HH];
__device__ float g_sum[HH];                    // zero-init; self-zeroed by bnfin
__device__ float g_sumsq[HH];
__device__ float g_a[HH];
__device__ float g_bc[HH];
// CSR build + permuted edge data
__device__ int g_off[NN + 1];
__device__ int g_cursor[NN];
__device__ int g_tmp[NN];
__device__ int g_bsum[SCAN_B];
__device__ int g_srcp[EE];
__device__ float g_attr8[(size_t)EE * 8];
// bf16 hi/lo split GEMM operands
__device__ __nv_bfloat16 g_Ab[(size_t)NN * 1024];        // A' [M][2K], K<=512
__device__ __nv_bfloat16 g_B1[(size_t)LL * 768 * 512];   // B1' [3K=768][N=512] k-major
__device__ __nv_bfloat16 g_B2[(size_t)LL * 1536 * 256];  // B2' [3K=1536][N=256]

// ================= PTX helpers =================
__device__ __forceinline__ uint32_t smem_u32(const void* p) {
    uint32_t a;
    asm("{ .reg .u64 t; cvta.to.shared.u64 t, %1; cvt.u32.u64 %0, t; }" : "=r"(a) : "l"(p));
    return a;
}
__device__ __forceinline__ void cpa16(uint32_t dst, const void* src, int sz) {
    asm volatile("cp.async.cg.shared.global [%0], [%1], 16, %2;"
                 :: "r"(dst), "l"(src), "r"(sz) : "memory");
}
#define CP_COMMIT() asm volatile("cp.async.commit_group;" ::: "memory")
#define CP_WAIT1()  asm volatile("cp.async.wait_group 1;" ::: "memory")

#define LDSM_X4(r, addr) \
    asm volatile("ldmatrix.sync.aligned.m8n8.x4.shared.b16 {%0,%1,%2,%3}, [%4];" \
        : "=r"((r)[0]), "=r"((r)[1]), "=r"((r)[2]), "=r"((r)[3]) : "r"(addr))
#define LDSM_X4T(r, addr) \
    asm volatile("ldmatrix.sync.aligned.m8n8.x4.trans.shared.b16 {%0,%1,%2,%3}, [%4];" \
        : "=r"((r)[0]), "=r"((r)[1]), "=r"((r)[2]), "=r"((r)[3]) : "r"(addr))
#define MMA16816(d, a, b0, b1) \
    asm volatile("mma.sync.aligned.m16n8k16.row.col.f32.bf16.bf16.f32 " \
        "{%0,%1,%2,%3}, {%4,%5,%6,%7}, {%8,%9}, {%0,%1,%2,%3};" \
        : "+f"((d)[0]), "+f"((d)[1]), "+f"((d)[2]), "+f"((d)[3]) \
        : "r"((a)[0]), "r"((a)[1]), "r"((a)[2]), "r"((a)[3]), "r"(b0), "r"(b1))

// ---------------- bf16 pack ----------------
__device__ __forceinline__ uint32_t pk_bf2(float a, float b) {
    __nv_bfloat162 t = __floats2bfloat162_rn(a, b);
    return *(uint32_t*)&t;
}

// ---------------- setup: h init + cursor zero + convB, one kernel ----------------
#define NB1 (768 * 512)
#define NB2 (1536 * 256)
#define NBCONV ((LL * (NB1 + NB2)) / 256)
__global__ void k_setup(const int* __restrict__ x, const float* __restrict__ emb,
                        const float* __restrict__ W1, const float* __restrict__ W2, int M) {
    int bid = blockIdx.x, tid = threadIdx.x;
    if (bid < M) {
        g_h[(size_t)bid * DD + tid] = emb[(size_t)x[bid] * DD + tid];
        if (tid == 0) g_cursor[bid] = 0;
        return;
    }
    int idx = (bid - M) * 256 + tid;
    int l = idx / (NB1 + NB2);
    int r = idx % (NB1 + NB2);
    if (r < NB1) {
        int kk = r / 512, n = r % 512;
        int part = kk >> 8, k = kk & 255;
        float w = W1[(size_t)l * DD * HH + (size_t)k * HH + n];
        __nv_bfloat16 hi = __float2bfloat16(w);
        g_B1[(size_t)l * NB1 + r] =
            (part < 2) ? hi : __float2bfloat16(w - __bfloat162float(hi));
    } else {
        r -= NB1;
        int kk = r / 256, n = r % 256;
        int part = kk >> 9, k = kk & 511;
        float w = W2[(size_t)l * HH * DD + (size_t)k * DD + n];
        __nv_bfloat16 hi = __float2bfloat16(w);
        g_B2[(size_t)l * NB2 + r] =
            (part < 2) ? hi : __float2bfloat16(w - __bfloat162float(hi));
    }
}

// ---------------- CSR build (parallel scan) ----------------
__global__ void k_hist(const int* __restrict__ dst, int E) {
    int e = blockIdx.x * blockDim.x + threadIdx.x;
    if (e < E) atomicAdd(&g_cursor[dst[e]], 1);
}
__global__ void k_scan1(int M) {
    __shared__ int s[SCAN_B];
    int t = threadIdx.x;
    int i = blockIdx.x * SCAN_B + t;
    int v = (i < M) ? g_cursor[i] : 0;
    s[t] = v;
    __syncthreads();
    for (int d = 1; d < SCAN_B; d <<= 1) {
        int x = (t >= d) ? s[t - d] : 0;
        __syncthreads();
        s[t] += x;
        __syncthreads();
    }
    if (i < M) g_tmp[i] = s[t];
    if (t == SCAN_B - 1) g_bsum[blockIdx.x] = s[t];
}
__global__ void k_scan2(int NB) {
    __shared__ int s[SCAN_B];
    int t = threadIdx.x;
    int v = (t < NB) ? g_bsum[t] : 0;
    s[t] = v;
    __syncthreads();
    for (int d = 1; d < SCAN_B; d <<= 1) {
        int x = (t >= d) ? s[t - d] : 0;
        __syncthreads();
        s[t] += x;
        __syncthreads();
    }
    if (t < NB) g_bsum[t] = s[t] - v;  // exclusive
}
// writes g_off[i+1] AND sets cursor[i] = exclusive prefix (merged scan3 + setcur)
__global__ void k_scan3(int M) {
    int i = blockIdx.x * SCAN_B + threadIdx.x;
    if (i < M) {
        int incl = g_tmp[i] + g_bsum[blockIdx.x];
        g_off[i + 1] = incl;
        g_cursor[i] = incl - (g_tmp[i] - ((threadIdx.x > 0) ? 0 : 0)) ;
    }
    if (i == 0) g_off[0] = 0;
}
// NOTE: the expression above must equal exclusive prefix = incl - count[i].
// count[i] is not retrievable from tmp alone after scan, so recompute cursor
// separately below (k_setcur) to stay correct.
__global__ void k_setcur(int M) {
    int i = blockIdx.x * blockDim.x + threadIdx.x;
    if (i < M) g_cursor[i] = g_off[i];
}
__global__ void k_scatter(const int* __restrict__ src, const int* __restrict__ dst,
                          const float* __restrict__ attr, int E) {
    int e = blockIdx.x * blockDim.x + threadIdx.x;
    if (e < E) {
        int p = atomicAdd(&g_cursor[dst[e]], 1);
        g_srcp[p] = src[e];
        const float* at = attr + (size_t)e * 7;
        float* o = g_attr8 + (size_t)p * 8;
        *(float4*)(o) = make_float4(at[0], at[1], at[2], at[3]);
        *(float4*)(o + 4) = make_float4(at[4], at[5], at[6], 0.f);
    }
}

// ---------------- gather (+ fused A1' split-convert), reads g_h ----------------
__global__ void __launch_bounds__(256)
k_gather(const float* __restrict__ We, const float* __restrict__ be,
         const float* __restrict__ eps, int M) {
    int t = threadIdx.x;
    int cg = (t & 63) * 4;
    int n = blockIdx.x * 4 + (t >> 6);

    float4 w[7];
    #pragma unroll
    for (int k = 0; k < 7; k++) w[k] = *(const float4*)(We + k * DD + cg);
    float4 bev = *(const float4*)(be + cg);
    float e1 = 1.f + eps[0];

    if (n >= M) return;
    int p0 = g_off[n], p1 = g_off[n + 1];
    float4 acc = make_float4(0.f, 0.f, 0.f, 0.f);
    #pragma unroll 4
    for (int p = p0; p < p1; p++) {
        int s = g_srcp[p];
        float4 a0 = *(const float4*)(g_attr8 + (size_t)p * 8);
        float4 a1 = *(const float4*)(g_attr8 + (size_t)p * 8 + 4);
        float4 hv = *(const float4*)(g_h + (size_t)s * DD + cg);
        float4 emb = bev;
        emb.x = fmaf(a0.x, w[0].x, emb.x); emb.y = fmaf(a0.x, w[0].y, emb.y);
        emb.z = fmaf(a0.x, w[0].z, emb.z); emb.w = fmaf(a0.x, w[0].w, emb.w);
        emb.x = fmaf(a0.y, w[1].x, emb.x); emb.y = fmaf(a0.y, w[1].y, emb.y);
        emb.z = fmaf(a0.y, w[1].z, emb.z); emb.w = fmaf(a0.y, w[1].w, emb.w);
        emb.x = fmaf(a0.z, w[2].x, emb.x); emb.y = fmaf(a0.z, w[2].y, emb.y);
        emb.z = fmaf(a0.z, w[2].z, emb.z); emb.w = fmaf(a0.z, w[2].w, emb.w);
        emb.x = fmaf(a0.w, w[3].x, emb.x); emb.y = fmaf(a0.w, w[3].y, emb.y);
        emb.z = fmaf(a0.w, w[3].z, emb.z); emb.w = fmaf(a0.w, w[3].w, emb.w);
        emb.x = fmaf(a1.x, w[4].x, emb.x); emb.y = fmaf(a1.x, w[4].y, emb.y);
        emb.z = fmaf(a1.x, w[4].z, emb.z); emb.w = fmaf(a1.x, w[4].w, emb.w);
        emb.x = fmaf(a1.y, w[5].x, emb.x); emb.y = fmaf(a1.y, w[5].y, emb.y);
        emb.z = fmaf(a1.y, w[5].z, emb.z); emb.w = fmaf(a1.y, w[5].w, emb.w);
        emb.x = fmaf(a1.z, w[6].x, emb.x); emb.y = fmaf(a1.z, w[6].y, emb.y);
        emb.z = fmaf(a1.z, w[6].z, emb.z); emb.w = fmaf(a1.z, w[6].w, emb.w);
        acc.x += fmaxf(hv.x + emb.x, 0.f);
        acc.y += fmaxf(hv.y + emb.y, 0.f);
        acc.z += fmaxf(hv.z + emb.z, 0.f);
        acc.w += fmaxf(hv.w + emb.w, 0.f);
    }
    float4 hn = *(const float4*)(g_h + (size_t)n * DD + cg);
    float v0 = fmaf(e1, hn.x, acc.x), v1 = fmaf(e1, hn.y, acc.y);
    float v2 = fmaf(e1, hn.z, acc.z), v3 = fmaf(e1, hn.w, acc.w);
    float h0 = __bfloat162float(__float2bfloat16(v0));
    float h1 = __bfloat162float(__float2bfloat16(v1));
    float h2 = __bfloat162float(__float2bfloat16(v2));
    float h3 = __bfloat162float(__float2bfloat16(v3));
    uint2 hi = make_uint2(pk_bf2(h0, h1), pk_bf2(h2, h3));
    uint2 lo = make_uint2(pk_bf2(v0 - h0, v1 - h1), pk_bf2(v2 - h2, v3 - h3));
    *(uint2*)(g_Ab + (size_t)n * 512 + cg) = hi;
    *(uint2*)(g_Ab + (size_t)n * 512 + 256 + cg) = lo;
}

// A2' = split(relu(t1*a + bc)), [M][1024]
__global__ void k_convA2(int M) {
    int idx = blockIdx.x * 256 + threadIdx.x;
    if (idx >= M * 128) return;
    int row = idx >> 7, k = (idx & 127) * 4;
    size_t off = (size_t)row * HH + k;
    float4 t4 = *(const float4*)(g_t1 + off);
    float4 ca = *(const float4*)(g_a + k);
    float4 cb = *(const float4*)(g_bc + k);
    float v0 = fmaxf(fmaf(t4.x, ca.x, cb.x), 0.f);
    float v1 = fmaxf(fmaf(t4.y, ca.y, cb.y), 0.f);
    float v2 = fmaxf(fmaf(t4.z, ca.z, cb.z), 0.f);
    float v3 = fmaxf(fmaf(t4.w, ca.w, cb.w), 0.f);
    float h0 = __bfloat162float(__float2bfloat16(v0));
    float h1 = __bfloat162float(__float2bfloat16(v1));
    float h2 = __bfloat162float(__float2bfloat16(v2));
    float h3 = __bfloat162float(__float2bfloat16(v3));
    uint2 hi = make_uint2(pk_bf2(h0, h1), pk_bf2(h2, h3));
    uint2 lo = make_uint2(pk_bf2(v0 - h0, v1 - h1), pk_bf2(v2 - h2, v3 - h3));
    *(uint2*)(g_Ab + (size_t)row * 1024 + k) = hi;
    *(uint2*)(g_Ab + (size_t)row * 1024 + 512 + k) = lo;
}

// ---------------- HMMA GEMM (R10 exact): 3-stage, 2 CTAs/SM --------------------
#define AP 80
#define BP 272
#define ASTG 10240
#define BSTG 8704
#define GSMEM (3 * (ASTG + BSTG) + 1024)

template <int NIT, int WRAP, int NC>
__global__ void __launch_bounds__(256, 2)
k_gemm_mma(const __nv_bfloat16* __restrict__ Abase, const __nv_bfloat16* __restrict__ Bbase,
           float* __restrict__ C, int M) {
    extern __shared__ char smem[];
    uint32_t sb = smem_u32(smem);
    uint32_t aB = sb, bB = sb + 3 * ASTG;
    float* ssum = (float*)(smem + 3 * (ASTG + BSTG));
    float* ssq = ssum + 128;

    int tid = threadIdx.x, lane = tid & 31, wid = tid >> 5;
    int wm = wid >> 1, wn = wid & 1;
    int brow = blockIdx.y * 128, bcol = blockIdx.x * 128;

    if (tid < 128) { ssum[tid] = 0.f; ssq[tid] = 0.f; }

    float acc[2][8][4];
    #pragma unroll
    for (int i = 0; i < 2; i++)
        #pragma unroll
        for (int j = 0; j < 8; j++)
            #pragma unroll
            for (int q = 0; q < 4; q++) acc[i][j][q] = 0.f;

    int arow = tid >> 1, ac16 = (tid & 1) * 2;
    int bkr = tid >> 3, bc16 = (tid & 7) * 2;

    auto load = [&](int s, int it) {
        int ac = it * 32; if (ac >= WRAP) ac -= WRAP;
        int ok = (brow + arow < M) ? 16 : 0;
        const char* srcA = (const char*)(Abase + (size_t)(brow + arow) * WRAP + ac);
        uint32_t dA = aB + s * ASTG + arow * AP;
        cpa16(dA + ac16 * 16, srcA + ac16 * 16, ok);
        cpa16(dA + ac16 * 16 + 16, srcA + ac16 * 16 + 16, ok);
        const char* srcB = (const char*)(Bbase + (size_t)(it * 32 + bkr) * NC + bcol);
        uint32_t dB = bB + s * BSTG + bkr * BP;
        cpa16(dB + bc16 * 16, srcB + bc16 * 16, 16);
        cpa16(dB + bc16 * 16 + 16, srcB + bc16 * 16 + 16, 16);
    };

    load(0, 0); CP_COMMIT();
    load(1, 1); CP_COMMIT();

    for (int i = 0; i < NIT; i++) {
        CP_WAIT1();
        __syncthreads();
        if (i + 2 < NIT) load((i + 2) % 3, i + 2);
        CP_COMMIT();

        int s = i % 3;
        uint32_t ab = aB + s * ASTG, bb = bB + s * BSTG;
        uint32_t a[2][2][4];
        #pragma unroll
        for (int mt = 0; mt < 2; mt++)
            #pragma unroll
            for (int kh = 0; kh < 2; kh++)
                LDSM_X4(a[mt][kh],
                        ab + (wm * 32 + mt * 16 + (lane & 15)) * AP +
                             (kh * 16 + (lane >> 4) * 8) * 2);
        #pragma unroll
        for (int nt2 = 0; nt2 < 4; nt2++) {
            uint32_t b0[4], b1[4];
            LDSM_X4T(b0, bb + (lane & 15) * BP +
                         (wn * 64 + nt2 * 16 + (lane >> 4) * 8) * 2);
            LDSM_X4T(b1, bb + (16 + (lane & 15)) * BP +
                         (wn * 64 + nt2 * 16 + (lane >> 4) * 8) * 2);
            #pragma unroll
            for (int mt = 0; mt < 2; mt++)
                #pragma unroll
                for (int j = 0; j < 2; j++) {
                    MMA16816(acc[mt][nt2 * 2 + j], a[mt][0], b0[j * 2], b0[j * 2 + 1]);
                    MMA16816(acc[mt][nt2 * 2 + j], a[mt][1], b1[j * 2], b1[j * 2 + 1]);
                }
        }
    }
    __syncthreads();

    // ---- epilogue: store C + fused BN stats ----
    int r0 = brow + wm * 32 + (lane >> 2);
    int cb = bcol + wn * 64 + (lane & 3) * 2;
    #pragma unroll
    for (int mt = 0; mt < 2; mt++)
        #pragma unroll
        for (int rh = 0; rh < 2; rh++) {
            int row = r0 + mt * 16 + rh * 8;
            if (row < M) {
                float* cr = C + (size_t)row * NC + cb;
                #pragma unroll
                for (int nt = 0; nt < 8; nt++)
                    *(float2*)(cr + nt * 8) =
                        make_float2(acc[mt][nt][rh * 2], acc[mt][nt][rh * 2 + 1]);
            }
        }
    #pragma unroll
    for (int nt = 0; nt < 8; nt++) {
        float s0 = 0.f, s1 = 0.f, q0 = 0.f, q1 = 0.f;
        #pragma unroll
        for (int mt = 0; mt < 2; mt++)
            #pragma unroll
            for (int rh = 0; rh < 2; rh++) {
                if (r0 + mt * 16 + rh * 8 < M) {
                    float v0 = acc[mt][nt][rh * 2], v1 = acc[mt][nt][rh * 2 + 1];
                    s0 += v0; q0 = fmaf(v0, v0, q0);
                    s1 += v1; q1 = fmaf(v1, v1, q1);
                }
            }
        int c = wn * 64 + nt * 8 + (lane & 3) * 2;
        atomicAdd(&ssum[c], s0);
        atomicAdd(&ssum[c + 1], s1);
        atomicAdd(&ssq[c], q0);
        atomicAdd(&ssq[c + 1], q1);
    }
    __syncthreads();
    if (tid < 128) {
        atomicAdd(&g_sum[bcol + tid], ssum[tid]);
        atomicAdd(&g_sumsq[bcol + tid], ssq[tid]);
    }
}

// ---------------- BN finalize (+ self-zero stats) ----------------
__global__ void k_bnfin(const float* __restrict__ g, const float* __restrict__ bt, float invM) {
    int c = blockIdx.x * blockDim.x + threadIdx.x;
    float mu = g_sum[c] * invM;
    float var = fmaf(-mu, mu, g_sumsq[c] * invM);
    float a = g[c] * rsqrtf(var + 1e-5f);
    g_a[c] = a;
    g_bc[c] = fmaf(-mu, a, bt[c]);
    g_sum[c] = 0.f;
    g_sumsq[c] = 0.f;
}

// ---------------- apply BN2 (+relu) ----------------
template <int TO_OUT>
__global__ void k_apply(float* __restrict__ out, int relu) {
    int idx = blockIdx.x * blockDim.x + threadIdx.x;
    float4 v = ((const float4*)g_agg)[idx];
    int c = (idx * 4) & (DD - 1);
    float4 a = *(const float4*)(g_a + c);
    float4 b = *(const float4*)(g_bc + c);
    v.x = fmaf(v.x, a.x, b.x);
    v.y = fmaf(v.y, a.y, b.y);
    v.z = fmaf(v.z, a.z, b.z);
    v.w = fmaf(v.w, a.w, b.w);
    if (relu) {
        v.x = fmaxf(v.x, 0.f); v.y = fmaxf(v.y, 0.f);
        v.z = fmaxf(v.z, 0.f); v.w = fmaxf(v.w, 0.f);
    }
    if (TO_OUT) ((float4*)out)[idx] = v;
    else        ((float4*)g_h)[idx] = v;
}

// ---------------- launcher ----------------
extern "C" void kernel_launch(void* const* d_in, const int* in_sizes, int n_in,
                              void* d_out, int out_size) {
    const int*   x        = (const int*)d_in[0];
    const int*   ei       = (const int*)d_in[1];
    const float* attr     = (const float*)d_in[2];
    const float* node_emb = (const float*)d_in[4];
    const float* We       = (const float*)d_in[5];
    const float* be       = (const float*)d_in[6];
    const float* W1       = (const float*)d_in[7];
    const float* g1       = (const float*)d_in[9];
    const float* bt1      = (const float*)d_in[10];
    const float* W2       = (const float*)d_in[11];
    const float* eps      = (const float*)d_in[13];
    const float* gbn      = (const float*)d_in[14];
    const float* bbn      = (const float*)d_in[15];
    float* out = (float*)d_out;

    int M = in_sizes[0];
    int E = in_sizes[1] / 2;
    const int* dst = ei + E;
    float invM = 1.0f / (float)M;

    // DEVICE addresses of __device__ globals
    void *pAb, *pB1, *pB2, *pT1, *pAgg;
    cudaGetSymbolAddress(&pAb, g_Ab);
    cudaGetSymbolAddress(&pB1, g_B1);
    cudaGetSymbolAddress(&pB2, g_B2);
    cudaGetSymbolAddress(&pT1, g_t1);
    cudaGetSymbolAddress(&pAgg, g_agg);
    const __nv_bfloat16* dAb = (const __nv_bfloat16*)pAb;
    const __nv_bfloat16* dB1 = (const __nv_bfloat16*)pB1;
    const __nv_bfloat16* dB2 = (const __nv_bfloat16*)pB2;
    float* dT1 = (float*)pT1;
    float* dAgg = (float*)pAgg;

    cudaFuncSetAttribute(k_gemm_mma<24, 512, 512>,
                         cudaFuncAttributeMaxDynamicSharedMemorySize, GSMEM);
    cudaFuncSetAttribute(k_gemm_mma<48, 1024, 256>,
                         cudaFuncAttributeMaxDynamicSharedMemorySize, GSMEM);

    int ewGrid = (M * DD / 4 + 255) / 256;
    int nb = (M + SCAN_B - 1) / SCAN_B;
    int ntm = (M + 127) / 128;
    dim3 g1grid(HH / 128, ntm), g2grid(DD / 128, ntm);

    // ---- setup + CSR build ----
    k_setup<<<M + NBCONV, 256>>>(x, node_emb, W1, W2, M);
    k_hist<<<(E + 255) / 256, 256>>>(dst, E);
    k_scan1<<<nb, SCAN_B>>>(M);
    k_scan2<<<1, SCAN_B>>>(nb);
    k_scan3<<<nb, SCAN_B>>>(M);
    k_setcur<<<(M + 255) / 256, 256>>>(M);
    k_scatter<<<(E + 255) / 256, 256>>>(ei, dst, attr, E);

    for (int l = 0; l < LL; l++) {
        k_gather<<<(M + 3) / 4, 256>>>(We + (size_t)l * 7 * DD, be + (size_t)l * DD,
                                       eps + l, M);

        k_gemm_mma<24, 512, 512><<<g1grid, 256, GSMEM>>>(
            dAb, dB1 + (size_t)l * 768 * 512, dT1, M);
        k_bnfin<<<HH / 256, 256>>>(g1 + (size_t)l * HH, bt1 + (size_t)l * HH, invM);

        k_convA2<<<(M * 128 + 255) / 256, 256>>>(M);
        k_gemm_mma<48, 1024, 256><<<g2grid, 256, GSMEM>>>(
            dAb, dB2 + (size_t)l * 1536 * 256, dAgg, M);
        k_bnfin<<<DD / 256, 256>>>(gbn + (size_t)l * DD, bbn + (size_t)l * DD, invM);

        if (l == LL - 1) k_apply<1><<<ewGrid, 256>>>(out, 0);
        else             k_apply<0><<<ewGrid, 256>>>(out, 1);
    }
}